// round 16
// baseline (speedup 1.0000x reference)
#include <cuda_runtime.h>
#include <cuda_fp16.h>
#include <cstdint>
#include <cstring>

#define D_DIM   11008
#define K_DIM   172
#define NKB     11           // k16 blocks for GEMM-1 (j = 0..175)
#define BP      72           // Bs row pitch in uint32 (288B) — bank-verified
#define OP      72           // Os staging pitch in floats
#define THREADS 128
// smem: Bs [88][BP] uint32 (25344B) + Os [172][OP] float (49536B) = 74880B
#define SMEM_BYTES (88 * BP * 4 + 172 * OP * 4)

static __device__ __forceinline__ uint32_t h2_bits(__half2 h) {
    uint32_t u;
    memcpy(&u, &h, 4);
    return u;
}

// had_K * (1/sqrt(D)) pre-packed into fp16 m16n8k16 A-fragment order (R9 layout):
//   block (mw, t, kb) -> 32 lanes -> uint4 {a0, a1, a2, a3}, one LDG.128 per (t,kb).
__device__ uint4 g_hKh[4 * 3 * NKB * 32];

__global__ void prep_hk(const float* __restrict__ hK) {
    int idx = blockIdx.x * blockDim.x + threadIdx.x;
    if (idx >= 4 * 3 * NKB * 32) return;
    int lane = idx & 31;
    int kb   = (idx >> 5) % NKB;
    int t    = (idx >> 5) / NKB % 3;
    int mw   = (idx >> 5) / (NKB * 3);
    int q = lane >> 2, p = lane & 3;
    int i  = mw * 48 + t * 16 + q;
    int k0 = 16 * kb + 2 * p;
    const float scale = rsqrtf((float)D_DIM);   // fold 1/sqrt(D) into hK
    float f[8];
    #pragma unroll
    for (int e = 0; e < 8; ++e) {
        int ii = i + ((e >> 1) & 1) * 8;
        int kk = k0 + (e >> 2) * 8 + (e & 1);
        f[e] = (ii < K_DIM && kk < K_DIM) ? hK[ii * K_DIM + kk] * scale : 0.f;
    }
    uint4 r;
    r.x = h2_bits(__floats2half2_rn(f[0], f[1]));
    r.y = h2_bits(__floats2half2_rn(f[2], f[3]));
    r.z = h2_bits(__floats2half2_rn(f[4], f[5]));
    r.w = h2_bits(__floats2half2_rn(f[6], f[7]));
    g_hKh[idx] = r;
}

__global__ __launch_bounds__(THREADS, 3)
void had_mma_kernel(const float* __restrict__ x,
                    float* __restrict__ out)
{
    extern __shared__ uint32_t Bs[];           // [88][BP] half2 pair-packed Xr
    float* Os = (float*)(Bs + 88 * BP);        // [172][OP] f32 output stage (disjoint!)
    const int tid  = threadIdx.x;
    const int w    = tid >> 5;                 // 0..3 (= mw, M-tile)
    const int lane = tid & 31;
    const int q    = lane >> 2;                // 0..7
    const int p    = lane & 3;                 // 0..3
    const int row  = blockIdx.x;

    // H_64 fragment constants (Sylvester, R11-validated): hA or hA^signflip.
    const uint32_t pq = (uint32_t)(__popc(p & (q >> 1)) & 1);
    const uint32_t t0 = (uint32_t)(q & 1);
    const uint32_t hA  = 0x3C003C00u | (pq << 15) | ((pq ^ t0) << 31);
    const uint32_t hAf = hA ^ 0x80008000u;

    // ---------- Phase 1: float4 bulk load -> half2 pair-packed Bs (R13-proven) ----------
    {
        const float* xr = x + (size_t)row * D_DIM;
        const int s  = lane >> 4;            // 0..1
        const int mg = lane & 15;            // m/4 group
        #pragma unroll
        for (int k2 = 0; k2 < 11; ++k2) {
            const int c2 = 2 * w + s + 8 * k2;
            float4 lo = make_float4(0.f, 0.f, 0.f, 0.f);
            float4 hi = lo;
            if (c2 < 86) {
                const float* bp = xr + (size_t)c2 * 128 + 4 * mg;
                lo = *(const float4*)(bp);
                hi = *(const float4*)(bp + 64);
            }
            uint4 pk;
            pk.x = h2_bits(__floats2half2_rn(lo.x, hi.x));
            pk.y = h2_bits(__floats2half2_rn(lo.y, hi.y));
            pk.z = h2_bits(__floats2half2_rn(lo.z, hi.z));
            pk.w = h2_bits(__floats2half2_rn(lo.w, hi.w));
            *(uint4*)(Bs + c2 * BP + 4 * mg) = pk;
        }
    }
    __syncthreads();

    // ---------- Phase 2: T = (hK/sqrtD) @ Xr via m16n8k16 fp16 (4M x 1N warps) ----------
    float acc[3][8][4];
    #pragma unroll
    for (int t = 0; t < 3; ++t)
        #pragma unroll
        for (int u = 0; u < 8; ++u)
            #pragma unroll
            for (int e = 0; e < 4; ++e) acc[t][u][e] = 0.f;

    const uint4* Aw = g_hKh + (size_t)(w * 3) * NKB * 32 + lane;

    #pragma unroll 2
    for (int kb = 0; kb < NKB; ++kb) {
        uint32_t b0[8], b1[8];
        const uint32_t* br = Bs + (8 * kb + p) * BP + q;
        #pragma unroll
        for (int u = 0; u < 8; ++u) {
            b0[u] = br[8 * u];                // k = 16kb+2p, +1
            b1[u] = br[8 * u + 4 * BP];       // k = 16kb+2p+8, +9
        }
        #pragma unroll
        for (int t = 0; t < 3; ++t) {
            uint4 a = Aw[(size_t)(t * NKB + kb) * 32];   // one coalesced LDG.128
            #pragma unroll
            for (int u = 0; u < 8; ++u) {
                asm volatile(
                    "mma.sync.aligned.m16n8k16.row.col.f32.f16.f16.f32 "
                    "{%0,%1,%2,%3}, {%4,%5,%6,%7}, {%8,%9}, {%0,%1,%2,%3};"
                    : "+f"(acc[t][u][0]), "+f"(acc[t][u][1]),
                      "+f"(acc[t][u][2]), "+f"(acc[t][u][3])
                    : "r"(a.x), "r"(a.y), "r"(a.z), "r"(a.w),
                      "r"(b0[u]), "r"(b1[u]));
            }
        }
    }

    // ---------- Phase 3: out = T @ H_64 -> smem stage (2-wf STS instead of 8-wf STG) ----------
    {
        const int i0 = w * 48;
        #pragma unroll
        for (int t = 0; t < 3; ++t) {
            float a2c[8][4];
            #pragma unroll
            for (int u = 0; u < 8; ++u)
                #pragma unroll
                for (int e = 0; e < 4; ++e) a2c[u][e] = 0.f;

            #pragma unroll
            for (int v = 0; v < 4; ++v) {
                const uint32_t a0 = h2_bits(__floats2half2_rn(acc[t][2*v  ][0], acc[t][2*v  ][1]));
                const uint32_t a1 = h2_bits(__floats2half2_rn(acc[t][2*v  ][2], acc[t][2*v  ][3]));
                const uint32_t a2 = h2_bits(__floats2half2_rn(acc[t][2*v+1][0], acc[t][2*v+1][1]));
                const uint32_t a3 = h2_bits(__floats2half2_rn(acc[t][2*v+1][2], acc[t][2*v+1][3]));
                #pragma unroll
                for (int u = 0; u < 8; ++u) {
                    // sign flips (R11-validated)
                    const int c0s = (((v & 1) & ((u >> 1) & 1)) ^ (((v >> 1) & 1) & ((u >> 2) & 1)));
                    const int c1s = c0s ^ (u & 1);
                    const uint32_t hb0 = c0s ? hAf : hA;
                    const uint32_t hb1 = c1s ? hAf : hA;
                    asm volatile(
                        "mma.sync.aligned.m16n8k16.row.col.f32.f16.f16.f32 "
                        "{%0,%1,%2,%3}, {%4,%5,%6,%7}, {%8,%9}, {%0,%1,%2,%3};"
                        : "+f"(a2c[u][0]), "+f"(a2c[u][1]),
                          "+f"(a2c[u][2]), "+f"(a2c[u][3])
                        : "r"(a0), "r"(a1), "r"(a2), "r"(a3),
                          "r"(hb0), "r"(hb1));
                }
            }
            // stage to smem (STS.64, bank-conflict-free at pitch 72)
            const int ib = i0 + t * 16 + q;
            #pragma unroll
            for (int u = 0; u < 8; ++u) {
                const int m = u * 8 + 2 * p;
                if (ib < K_DIM)
                    *(float2*)(Os + ib * OP + m) = make_float2(a2c[u][0], a2c[u][1]);
                if (ib + 8 < K_DIM)
                    *(float2*)(Os + (ib + 8) * OP + m) = make_float2(a2c[u][2], a2c[u][3]);
            }
        }
    }
    __syncthreads();

    // ---------- Phase 4: bulk coalesced copy-out (LDS.128 + streaming STG.128) ----------
    {
        float4* orow4 = (float4*)(out + (size_t)row * D_DIM);
        // 172*64 floats = 2752 float4; conflict-free LDS.128 + fully coalesced STG.128
        for (int u4 = tid; u4 < (K_DIM * 64) / 4; u4 += THREADS) {
            const int i  = u4 >> 4;
            const int m4 = u4 & 15;
            float4 v = *(const float4*)(Os + i * OP + m4 * 4);
            __stcs(orow4 + u4, v);      // streaming: out is never re-read
        }
    }
}

extern "C" void kernel_launch(void* const* d_in, const int* in_sizes, int n_in,
                              void* d_out, int out_size)
{
    const float* x  = (const float*)d_in[0];
    const float* hK = (const float*)d_in[1];
    int nx = in_sizes[0];
    if (n_in > 1 && in_sizes[0] == K_DIM * K_DIM) {   // defensive input-order check
        x  = (const float*)d_in[1];
        hK = (const float*)d_in[0];
        nx = in_sizes[1];
    }
    float* out = (float*)d_out;
    const int nrows = nx / D_DIM;

    cudaFuncSetAttribute(had_mma_kernel,
                         cudaFuncAttributeMaxDynamicSharedMemorySize, SMEM_BYTES);

    prep_hk<<<(4 * 3 * NKB * 32 + 255) / 256, 256>>>(hK);
    had_mma_kernel<<<nrows, THREADS, SMEM_BYTES>>>(x, out);
}

// round 17
// speedup vs baseline: 1.1890x; 1.1890x over previous
#include <cuda_runtime.h>
#include <cuda_fp16.h>
#include <cstdint>
#include <cstring>

#define D_DIM   11008
#define K_DIM   172
#define NKB     11           // k16 blocks for GEMM-1 (j = 0..175)
#define BP      72           // Bs row pitch in uint32 (288B) — bank-verified
#define THREADS 128
#define SMEM_BYTES (88 * BP * 4)   // 25344 (keeps L1D large for A-operand hits)

static __device__ __forceinline__ uint32_t h2_bits(__half2 h) {
    uint32_t u;
    memcpy(&u, &h, 4);
    return u;
}

// had_K * (1/sqrt(D)) pre-packed into fp16 m16n8k16 A-fragment order (R9 layout):
//   block (mw, t, kb) -> 32 lanes -> uint4 {a0, a1, a2, a3}, one LDG.128 per (t,kb).
__device__ uint4 g_hKh[4 * 3 * NKB * 32];

__global__ void prep_hk(const float* __restrict__ hK) {
    int idx = blockIdx.x * blockDim.x + threadIdx.x;
    if (idx >= 4 * 3 * NKB * 32) return;
    int lane = idx & 31;
    int kb   = (idx >> 5) % NKB;
    int t    = (idx >> 5) / NKB % 3;
    int mw   = (idx >> 5) / (NKB * 3);
    int q = lane >> 2, p = lane & 3;
    int i  = mw * 48 + t * 16 + q;
    int k0 = 16 * kb + 2 * p;
    const float scale = rsqrtf((float)D_DIM);   // fold 1/sqrt(D) into hK
    float f[8];
    #pragma unroll
    for (int e = 0; e < 8; ++e) {
        int ii = i + ((e >> 1) & 1) * 8;
        int kk = k0 + (e >> 2) * 8 + (e & 1);
        f[e] = (ii < K_DIM && kk < K_DIM) ? hK[ii * K_DIM + kk] * scale : 0.f;
    }
    uint4 r;
    r.x = h2_bits(__floats2half2_rn(f[0], f[1]));
    r.y = h2_bits(__floats2half2_rn(f[2], f[3]));
    r.z = h2_bits(__floats2half2_rn(f[4], f[5]));
    r.w = h2_bits(__floats2half2_rn(f[6], f[7]));
    g_hKh[idx] = r;
}

__global__ __launch_bounds__(THREADS, 3)
void had_mma_kernel(const float* __restrict__ x,
                    float* __restrict__ out)
{
    extern __shared__ uint32_t Bs[];   // [88][BP] half2 pair-packed Xr
    const int tid  = threadIdx.x;
    const int w    = tid >> 5;               // 0..3 (= mw, M-tile)
    const int lane = tid & 31;
    const int q    = lane >> 2;              // 0..7
    const int p    = lane & 3;               // 0..3
    const int row  = blockIdx.x;

    // H8 B-fragment constant for stage-2 (m16n8k8, n=q, k=2p..2p+1):
    //   lo sign = popc(q & 2p) = popc(p & (q>>1));  hi sign = lo ^ (q&1).
    //   (Identical bit pattern to the R11-validated H64 constant.)
    const uint32_t pq = (uint32_t)(__popc(p & (q >> 1)) & 1);
    const uint32_t t0 = (uint32_t)(q & 1);
    const uint32_t hA = 0x3C003C00u | (pq << 15) | ((pq ^ t0) << 31);

    // ---------- Phase 1: float4 bulk load -> half2 pair-packed Bs (R13-proven) ----------
    {
        const float* xr = x + (size_t)row * D_DIM;
        const int s  = lane >> 4;            // 0..1
        const int mg = lane & 15;            // m/4 group
        #pragma unroll
        for (int k2 = 0; k2 < 11; ++k2) {
            const int c2 = 2 * w + s + 8 * k2;
            float4 lo = make_float4(0.f, 0.f, 0.f, 0.f);
            float4 hi = lo;
            if (c2 < 86) {
                const float* bp = xr + (size_t)c2 * 128 + 4 * mg;
                lo = *(const float4*)(bp);
                hi = *(const float4*)(bp + 64);
            }
            uint4 pk;
            pk.x = h2_bits(__floats2half2_rn(lo.x, hi.x));
            pk.y = h2_bits(__floats2half2_rn(lo.y, hi.y));
            pk.z = h2_bits(__floats2half2_rn(lo.z, hi.z));
            pk.w = h2_bits(__floats2half2_rn(lo.w, hi.w));
            *(uint4*)(Bs + c2 * BP + 4 * mg) = pk;
        }
    }
    __syncthreads();

    // ---------- Phase 2: T = (hK/sqrtD) @ Xr via m16n8k16 fp16 (4M x 1N warps) ----------
    float acc[3][8][4];
    #pragma unroll
    for (int t = 0; t < 3; ++t)
        #pragma unroll
        for (int u = 0; u < 8; ++u)
            #pragma unroll
            for (int e = 0; e < 4; ++e) acc[t][u][e] = 0.f;

    const uint4* Aw = g_hKh + (size_t)(w * 3) * NKB * 32 + lane;

    #pragma unroll 2
    for (int kb = 0; kb < NKB; ++kb) {
        uint32_t b0[8], b1[8];
        const uint32_t* br = Bs + (8 * kb + p) * BP + q;
        #pragma unroll
        for (int u = 0; u < 8; ++u) {
            b0[u] = br[8 * u];                // k = 16kb+2p, +1
            b1[u] = br[8 * u + 4 * BP];       // k = 16kb+2p+8, +9
        }
        #pragma unroll
        for (int t = 0; t < 3; ++t) {
            uint4 a = Aw[(size_t)(t * NKB + kb) * 32];   // one coalesced LDG.128
            #pragma unroll
            for (int u = 0; u < 8; ++u) {
                asm volatile(
                    "mma.sync.aligned.m16n8k16.row.col.f32.f16.f16.f32 "
                    "{%0,%1,%2,%3}, {%4,%5,%6,%7}, {%8,%9}, {%0,%1,%2,%3};"
                    : "+f"(acc[t][u][0]), "+f"(acc[t][u][1]),
                      "+f"(acc[t][u][2]), "+f"(acc[t][u][3])
                    : "r"(a.x), "r"(a.y), "r"(a.z), "r"(a.w),
                      "r"(b0[u]), "r"(b1[u]));
            }
        }
    }

    // ---------- Phase 3: out = T @ H64 via H64 = H8 (x) H8 ----------
    // m = 8*a1 + a0 with a1 = u (register index!), a0 = 2p + (e&1) (fragment k!).
    // Stage 1: exact fp32 FWHT-8 over u (per t, per e) — reduces a1.
    // Stage 2: one m16n8k8 MMA per (t, u') with constant-register B = H8 — reduces a0.
    {
        float* orow = out + (size_t)row * D_DIM;
        const int i0 = w * 48;
        #pragma unroll
        for (int t = 0; t < 3; ++t) {
            // Stage 1: in-register butterfly over u, all 4 e-slots
            #pragma unroll
            for (int s = 1; s <= 4; s <<= 1) {
                #pragma unroll
                for (int u = 0; u < 8; ++u) {
                    if ((u & s) == 0) {
                        #pragma unroll
                        for (int e = 0; e < 4; ++e) {
                            float a = acc[t][u][e], b = acc[t][u + s][e];
                            acc[t][u][e]     = a + b;
                            acc[t][u + s][e] = a - b;
                        }
                    }
                }
            }
            const int ib = i0 + t * 16 + q;
            // Stage 2: per u', pack A-fragment and issue one k8 MMA, store immediately
            #pragma unroll
            for (int u = 0; u < 8; ++u) {
                const uint32_t pa = h2_bits(__floats2half2_rn(acc[t][u][0], acc[t][u][1])); // row q,  k=2p,2p+1
                const uint32_t pb = h2_bits(__floats2half2_rn(acc[t][u][2], acc[t][u][3])); // row q+8
                float d0, d1, d2, d3;
                asm volatile(
                    "mma.sync.aligned.m16n8k8.row.col.f32.f16.f16.f32 "
                    "{%0,%1,%2,%3}, {%4,%5}, {%6}, {%7,%8,%9,%10};"
                    : "=f"(d0), "=f"(d1), "=f"(d2), "=f"(d3)
                    : "r"(pa), "r"(pb), "r"(hA),
                      "f"(0.f), "f"(0.f), "f"(0.f), "f"(0.f));
                // direct store (8-row x 32B runs), col m' = 8u + 2p
                const int m = u * 8 + 2 * p;
                if (ib < K_DIM)
                    *(float2*)(orow + ib * 64 + m) = make_float2(d0, d1);
                if (ib + 8 < K_DIM)
                    *(float2*)(orow + (ib + 8) * 64 + m) = make_float2(d2, d3);
            }
        }
    }
}

extern "C" void kernel_launch(void* const* d_in, const int* in_sizes, int n_in,
                              void* d_out, int out_size)
{
    const float* x  = (const float*)d_in[0];
    const float* hK = (const float*)d_in[1];
    int nx = in_sizes[0];
    if (n_in > 1 && in_sizes[0] == K_DIM * K_DIM) {   // defensive input-order check
        x  = (const float*)d_in[1];
        hK = (const float*)d_in[0];
        nx = in_sizes[1];
    }
    float* out = (float*)d_out;
    const int nrows = nx / D_DIM;

    cudaFuncSetAttribute(had_mma_kernel,
                         cudaFuncAttributeMaxDynamicSharedMemorySize, SMEM_BYTES);

    prep_hk<<<(4 * 3 * NKB * 32 + 255) / 256, 256>>>(hK);
    had_mma_kernel<<<nrows, THREADS, SMEM_BYTES>>>(x, out);
}